// round 4
// baseline (speedup 1.0000x reference)
#include <cuda_runtime.h>
#include <cstdint>

#define BATCH 32768
#define IDIM  128
#define HDIM  256
#define ADIM  32
#define MT    64
#define NT    256
#define NBLK  (BATCH/MT)
#define NC    64

#define AST     36
#define ASM_SZ  (64*AST)            // 2304 floats
#define WSM_SZ  (192*AST)           // 6912 floats
#define BUF_SZ  (ASM_SZ+WSM_SZ)     // 9216 floats
#define SMEM_DYN (3*BUF_SZ*4)       // 110592 bytes

static __device__ __forceinline__ uint32_t smem_u32(const void* p) {
    uint32_t a;
    asm("{ .reg .u64 t; cvta.to.shared.u64 t, %1; cvt.u32.u64 %0, t; }"
        : "=r"(a) : "l"(p));
    return a;
}
static __device__ __forceinline__ float tf32r(float x) {
    float r; asm("cvt.rna.tf32.f32 %0, %1;" : "=f"(r) : "f"(x)); return r;
}
static __device__ __forceinline__ uint32_t ldc(const float* p) {
    return __float_as_uint(tf32r(*p));
}
static __device__ __forceinline__ void mma8(float c[4], const uint32_t a[4],
                                            const uint32_t b[2]) {
    asm volatile(
        "mma.sync.aligned.m16n8k8.row.col.f32.tf32.tf32.f32 "
        "{%0,%1,%2,%3},{%4,%5,%6,%7},{%8,%9},{%0,%1,%2,%3};"
        : "+f"(c[0]), "+f"(c[1]), "+f"(c[2]), "+f"(c[3])
        : "r"(a[0]), "r"(a[1]), "r"(a[2]), "r"(a[3]), "r"(b[0]), "r"(b[1]));
}
static __device__ __forceinline__ float sigf(float x) {
    return __fdividef(1.0f, 1.0f + __expf(-x));
}
static __device__ __forceinline__ float tanhff(float x) {
    float ax = fabsf(x), e = __expf(-2.0f * ax);
    return copysignf(__fdividef(1.0f - e, 1.0f + e), x);
}
static __device__ __forceinline__ float gru1(float rp, float zp, float ip,
                                             float hp, float hv) {
    float r = sigf(rp), z = sigf(zp);
    float n = tanhff(ip + r * hp);
    return n + z * (hv - n);
}

#define CP16(dst, src) \
    asm volatile("cp.async.cg.shared.global [%0], [%1], 16;" \
                 :: "r"(dst), "l"(src) : "memory")
#define CPC()  asm volatile("cp.async.commit_group;" ::: "memory")
#define CPW1() asm volatile("cp.async.wait_group 1;" ::: "memory")
#define CPW0() asm volatile("cp.async.wait_group 0;" ::: "memory")

__global__ void __launch_bounds__(NT, 2)
gru_ac_kernel(const float* __restrict__ x,    const float* __restrict__ hin,
              const float* __restrict__ wih0, const float* __restrict__ whh0,
              const float* __restrict__ bih0, const float* __restrict__ bhh0,
              const float* __restrict__ wih1, const float* __restrict__ whh1,
              const float* __restrict__ bih1, const float* __restrict__ bhh1,
              const float* __restrict__ wp,   const float* __restrict__ bp,
              const float* __restrict__ wv,   const float* __restrict__ bv,
              float* __restrict__ out)
{
    extern __shared__ float sm[];
    const uint32_t smb = smem_u32(sm);
    const int tid  = threadIdx.x;
    const int lane = tid & 31;
    const int wid  = tid >> 5;
    const int wm   = wid >> 2;     // 0..1 : 32-row band
    const int wn   = wid & 3;      // 0..3 : 16-col band
    const int gID  = lane >> 2;
    const int tig  = lane & 3;
    const int rowbase = blockIdx.x * MT;

    float* outL  = out;
    float* outV  = out + (size_t)BATCH * ADIM;
    float* hbase = out + (size_t)BATCH * (ADIM + 1);   // [2][B][H]

    // per-thread staging slots (float4 granularity)
    int ar[2], aj[2];
    #pragma unroll
    for (int i = 0; i < 2; ++i) {
        int s = tid + i * NT;           // 0..511
        ar[i] = s >> 3; aj[i] = s & 7;  // A row 0..63
    }
    int wg[6], wl[6], wj[6];
    #pragma unroll
    for (int i = 0; i < 6; ++i) {
        int s = tid + i * NT;           // 0..1535
        int row = s >> 3;               // 0..191
        wg[i] = row >> 6; wl[i] = row & 63; wj[i] = s & 7;
    }

    for (int layer = 0; layer < 2; ++layer) {
        const float* wih = layer ? wih1 : wih0;
        const float* whh = layer ? whh1 : whh0;
        const float* bih = layer ? bih1 : bih0;
        const float* bhh = layer ? bhh1 : bhh0;
        const int    KX  = layer ? HDIM : IDIM;
        const int    ncx = KX >> 5;
        const int    nk  = ncx + (HDIM >> 5);
        const float* asrcx = layer ? (hbase + (size_t)rowbase * HDIM)
                                   : (x + (size_t)rowbase * IDIM);
        const int    axs   = layer ? HDIM : IDIM;
        const float* asrch = hin + (size_t)layer * BATCH * HDIM
                                 + (size_t)rowbase * HDIM;
        float*       hdst  = hbase + (size_t)layer * BATCH * HDIM
                                   + (size_t)rowbase * HDIM;

        for (int q = 0; q < 4; ++q) {
            const int qc = q * NC;

            auto prefetch = [&](int kc, int buf) {
                const bool isX = kc < ncx;
                const float* ab  = isX ? asrcx : asrch;
                const int    as_ = isX ? axs : HDIM;
                const float* wb  = isX ? wih : whh;
                const int    wk  = isX ? KX : HDIM;
                const int    ko  = (isX ? kc : kc - ncx) << 5;
                uint32_t Ab = smb + buf * (BUF_SZ * 4);
                uint32_t Wb = Ab + ASM_SZ * 4;
                #pragma unroll
                for (int i = 0; i < 2; ++i)
                    CP16(Ab + (ar[i] * AST + aj[i] * 4) * 4,
                         ab + (size_t)ar[i] * as_ + ko + aj[i] * 4);
                #pragma unroll
                for (int i = 0; i < 6; ++i)
                    CP16(Wb + ((wg[i] * 64 + wl[i]) * AST + wj[i] * 4) * 4,
                         wb + (size_t)(wg[i] * 256 + qc + wl[i]) * wk
                            + ko + wj[i] * 4);
                CPC();
            };

            float aR[2][2][4], aZ[2][2][4], aI[2][2][4], aH[2][2][4];
            #pragma unroll
            for (int t = 0; t < 2; ++t)
                #pragma unroll
                for (int s = 0; s < 2; ++s)
                    #pragma unroll
                    for (int k = 0; k < 4; ++k) {
                        aR[t][s][k] = 0.f; aZ[t][s][k] = 0.f;
                        aI[t][s][k] = 0.f; aH[t][s][k] = 0.f;
                    }

            prefetch(0, 0);
            prefetch(1, 1);

            for (int kc = 0; kc < nk; ++kc) {
                if (kc + 1 < nk) { CPW1(); } else { CPW0(); }
                __syncthreads();
                if (kc + 2 < nk) prefetch(kc + 2, (kc + 2) % 3);

                const float* Ab = sm + (kc % 3) * BUF_SZ;
                const float* Wb = Ab + ASM_SZ;
                const bool isX = kc < ncx;

                #pragma unroll
                for (int kk = 0; kk < 4; ++kk) {
                    uint32_t af[2][4];
                    #pragma unroll
                    for (int t = 0; t < 2; ++t) {
                        const float* ap = Ab + (wm * 32 + t * 16 + gID) * AST
                                             + kk * 8 + tig;
                        af[t][0] = ldc(ap);
                        af[t][1] = ldc(ap + 8 * AST);
                        af[t][2] = ldc(ap + 4);
                        af[t][3] = ldc(ap + 8 * AST + 4);
                    }
                    #pragma unroll
                    for (int s = 0; s < 2; ++s) {
                        const int nr = wn * 16 + s * 8 + gID;
                        const float* w0 = Wb + nr * AST + kk * 8 + tig;
                        uint32_t bR[2], bZ[2], bN[2];
                        bR[0] = ldc(w0);
                        bR[1] = ldc(w0 + 4);
                        bZ[0] = ldc(w0 + 64 * AST);
                        bZ[1] = ldc(w0 + 64 * AST + 4);
                        bN[0] = ldc(w0 + 128 * AST);
                        bN[1] = ldc(w0 + 128 * AST + 4);
                        #pragma unroll
                        for (int t = 0; t < 2; ++t) {
                            mma8(aR[t][s], af[t], bR);
                            mma8(aZ[t][s], af[t], bZ);
                        }
                        if (isX) {
                            #pragma unroll
                            for (int t = 0; t < 2; ++t) mma8(aI[t][s], af[t], bN);
                        } else {
                            #pragma unroll
                            for (int t = 0; t < 2; ++t) mma8(aH[t][s], af[t], bN);
                        }
                    }
                }
            }

            // elementwise GRU gates from fragments (biases fused from gmem)
            #pragma unroll
            for (int s = 0; s < 2; ++s) {
                const int c = qc + wn * 16 + s * 8 + tig * 2;
                float2 bi0 = *(const float2*)&bih[c];
                float2 bh0 = *(const float2*)&bhh[c];
                float2 bi1 = *(const float2*)&bih[256 + c];
                float2 bh1 = *(const float2*)&bhh[256 + c];
                float2 bIv = *(const float2*)&bih[512 + c];
                float2 bHv = *(const float2*)&bhh[512 + c];
                float2 bRv = make_float2(bi0.x + bh0.x, bi0.y + bh0.y);
                float2 bZv = make_float2(bi1.x + bh1.x, bi1.y + bh1.y);
                #pragma unroll
                for (int t = 0; t < 2; ++t) {
                    const int ra = wm * 32 + t * 16 + gID;
                    const int rb = ra + 8;
                    float2 ha = *(const float2*)&asrch[(size_t)ra * HDIM + c];
                    float2 hb = *(const float2*)&asrch[(size_t)rb * HDIM + c];
                    float2 oa, ob;
                    oa.x = gru1(aR[t][s][0] + bRv.x, aZ[t][s][0] + bZv.x,
                                aI[t][s][0] + bIv.x, aH[t][s][0] + bHv.x, ha.x);
                    oa.y = gru1(aR[t][s][1] + bRv.y, aZ[t][s][1] + bZv.y,
                                aI[t][s][1] + bIv.y, aH[t][s][1] + bHv.y, ha.y);
                    ob.x = gru1(aR[t][s][2] + bRv.x, aZ[t][s][2] + bZv.x,
                                aI[t][s][2] + bIv.x, aH[t][s][2] + bHv.x, hb.x);
                    ob.y = gru1(aR[t][s][3] + bRv.y, aZ[t][s][3] + bZv.y,
                                aI[t][s][3] + bIv.y, aH[t][s][3] + bHv.y, hb.y);
                    *(float2*)&hdst[(size_t)ra * HDIM + c] = oa;
                    *(float2*)&hdst[(size_t)rb * HDIM + c] = ob;
                }
            }
            __syncthreads();   // hdst visible; smem bufs free for next q
        }
    }

    // heads: logits = h1 @ w_p^T + b_p ; value = h1 @ w_v^T + b_v
    {
        const int row = tid >> 2;              // 0..63
        const int qq  = tid & 3;               // 8 logits per thread
        const float* h1r = hbase + (size_t)BATCH * HDIM
                                 + (size_t)(rowbase + row) * HDIM;
        float acc[8];
        #pragma unroll
        for (int a = 0; a < 8; ++a) acc[a] = bp[qq * 8 + a];
        float av = bv[0];
        const float4* h4 = (const float4*)h1r;
        for (int kb = 0; kb < HDIM / 4; ++kb) {
            float4 hv = h4[kb];
            #pragma unroll
            for (int a = 0; a < 8; ++a) {
                const float4 wq =
                    *(const float4*)&wp[(qq * 8 + a) * HDIM + kb * 4];
                acc[a] += hv.x * wq.x + hv.y * wq.y + hv.z * wq.z + hv.w * wq.w;
            }
            if (qq == 0) {
                const float4 wq = *(const float4*)&wv[kb * 4];
                av += hv.x * wq.x + hv.y * wq.y + hv.z * wq.z + hv.w * wq.w;
            }
        }
        #pragma unroll
        for (int a = 0; a < 8; ++a)
            outL[(size_t)(rowbase + row) * ADIM + qq * 8 + a] = acc[a];
        if (qq == 0) outV[rowbase + row] = av;
    }
}

extern "C" void kernel_launch(void* const* d_in, const int* in_sizes, int n_in,
                              void* d_out, int out_size) {
    const float* x    = (const float*)d_in[0];
    const float* hin  = (const float*)d_in[1];
    const float* wih0 = (const float*)d_in[2];
    const float* whh0 = (const float*)d_in[3];
    const float* bih0 = (const float*)d_in[4];
    const float* bhh0 = (const float*)d_in[5];
    const float* wih1 = (const float*)d_in[6];
    const float* whh1 = (const float*)d_in[7];
    const float* bih1 = (const float*)d_in[8];
    const float* bhh1 = (const float*)d_in[9];
    const float* wp   = (const float*)d_in[10];
    const float* bp   = (const float*)d_in[11];
    const float* wv   = (const float*)d_in[12];
    const float* bv   = (const float*)d_in[13];
    float* out = (float*)d_out;

    cudaFuncSetAttribute(gru_ac_kernel,
                         cudaFuncAttributeMaxDynamicSharedMemorySize, SMEM_DYN);
    gru_ac_kernel<<<NBLK, NT, SMEM_DYN>>>(x, hin, wih0, whh0, bih0, bhh0,
                                          wih1, whh1, bih1, bhh1,
                                          wp, bp, wv, bv, out);
}